// round 8
// baseline (speedup 1.0000x reference)
#include <cuda_runtime.h>
#include <math.h>

#define NB 32
#define NC 1024
#define NM 1024
#define ND 512
#define NR 64

#define CS_SPLIT 32             // c-chunks for p2a (32 c each)
#define KS_SPLIT 16             // d-chunks for p2b (32 d each)
#define SCH 32                  // c-chunks for k_s (32 c each)
#define D_CH (ND / KS_SPLIT)    // 32
#define C_CH (NC / SCH)         // 32
#define ITILE 128               // i-tile for k_wout

// ---- device scratch (static: no allocations allowed) ----
__device__ float g_tsum[NB * NC];
__device__ float g_rsum[NR];
__device__ float g_kpart[CS_SPLIT][NB * ND];
__device__ float g_vpart[CS_SPLIT][NB * ND];
__device__ float g_upart[KS_SPLIT][NB * NC];
__device__ float g_ypart[KS_SPLIT][NB * NC];
__device__ float g_spart[SCH][NB * NM];

__device__ __forceinline__ float warp_sum(float v) {
    #pragma unroll
    for (int o = 16; o; o >>= 1) v += __shfl_down_sync(0xffffffffu, v, o);
    return v;
}

// pinned (compiler-unmovable) 128-bit non-coherent load
__device__ __forceinline__ float4 ldg128_pin(const float* p) {
    float4 v;
    asm volatile("ld.global.nc.v4.f32 {%0,%1,%2,%3}, [%4];"
                 : "=f"(v.x), "=f"(v.y), "=f"(v.z), "=f"(v.w)
                 : "l"(p));
    return v;
}

// ---------------------------------------------------------------------------
// k_tsum: blocks [0,4096): tsum[b,c] = sum_m T[b,c,m]  (warp/row; 8 pinned
//         float4 loads in flight before any reduction)
//         blocks [4096,4104): rsum[r] = sum_m R_full[r,m]
// ---------------------------------------------------------------------------
__global__ __launch_bounds__(256) void k_tsum(const float* __restrict__ T,
                                              const float* __restrict__ Rf) {
    int lane = threadIdx.x & 31;
    const float* src;
    if (blockIdx.x < 4096) {
        int row = blockIdx.x * 8 + (threadIdx.x >> 5);
        src = T + (size_t)row * NM;
    } else {
        int r = (blockIdx.x - 4096) * 8 + (threadIdx.x >> 5);   // 64 rows
        src = Rf + (size_t)r * NM;
    }
    float4 t[8];
    #pragma unroll
    for (int k = 0; k < 8; k++)
        t[k] = ldg128_pin(src + (k * 32 + lane) * 4);
    float acc = 0.f;
    #pragma unroll
    for (int k = 0; k < 8; k++)
        acc += (t[k].x + t[k].y) + (t[k].z + t[k].w);
    acc = warp_sum(acc);
    if (lane == 0) {
        if (blockIdx.x < 4096)
            g_tsum[blockIdx.x * 8 + (threadIdx.x >> 5)] = acc;
        else
            g_rsum[(blockIdx.x - 4096) * 8 + (threadIdx.x >> 5)] = acc;
    }
}

// ---------------------------------------------------------------------------
// k_p2a: kpart/vpart[cs][b,d] = sum_{c in chunk} tsum[b,c]*Wk/Wv[c,d]
// grid (ND/128, CS_SPLIT) x 128; thread owns d, acc[32] over b.
// ---------------------------------------------------------------------------
__global__ __launch_bounds__(128) void k_p2a(const float* __restrict__ Wk,
                                             const float* __restrict__ Wv) {
    __shared__ float ts[NB][32];
    int d  = blockIdx.x * 128 + threadIdx.x;
    int c0 = blockIdx.y * 32;
    for (int e = threadIdx.x; e < NB * 32; e += 128)
        ts[e >> 5][e & 31] = g_tsum[(e >> 5) * NC + c0 + (e & 31)];
    __syncthreads();

    float aK[NB], aV[NB];
    #pragma unroll
    for (int b = 0; b < NB; b++) { aK[b] = 0.f; aV[b] = 0.f; }

    #pragma unroll 4
    for (int cc = 0; cc < 32; cc++) {
        int c = c0 + cc;
        float wk = Wk[(size_t)c * ND + d];
        float wv = Wv[(size_t)c * ND + d];
        #pragma unroll
        for (int b = 0; b < NB; b++) {
            float tv = ts[b][cc];
            aK[b] = fmaf(tv, wk, aK[b]);
            aV[b] = fmaf(tv, wv, aV[b]);
        }
    }
    #pragma unroll
    for (int b = 0; b < NB; b++) {
        g_kpart[blockIdx.y][b * ND + d] = aK[b];
        g_vpart[blockIdx.y][b * ND + d] = aV[b];
    }
}

// ---------------------------------------------------------------------------
// k_p2b: fuses kv-partial reduction + both GEMMs (no Wq transpose).
//   upart[ks][b,c] = sum_{d in chunk} ksum[b,d]*Wq[c,d]
//   ypart[ks][b,c] = sum_{d in chunk} vsum[b,d]*Wout[d,c]
// grid (NC/128, KS_SPLIT) x 128; thread owns c.
// ---------------------------------------------------------------------------
__global__ __launch_bounds__(128) void k_p2b(const float* __restrict__ Wq,
                                             const float* __restrict__ Wout) {
    __shared__ float ks[NB][D_CH], vs[NB][D_CH];
    int c  = blockIdx.x * 128 + threadIdx.x;
    int d0 = blockIdx.y * D_CH;

    for (int e = threadIdx.x; e < NB * D_CH; e += 128) {
        int addr = (e >> 5) * ND + d0 + (e & (D_CH - 1));
        float sk = 0.f, sv = 0.f;
        #pragma unroll
        for (int p = 0; p < CS_SPLIT; p++) {
            sk += g_kpart[p][addr];
            sv += g_vpart[p][addr];
        }
        ks[e >> 5][e & (D_CH - 1)] = sk;
        vs[e >> 5][e & (D_CH - 1)] = sv;
    }
    __syncthreads();

    float wqr[D_CH];
    {
        const float4* wq4 = reinterpret_cast<const float4*>(Wq + (size_t)c * ND + d0);
        #pragma unroll
        for (int q = 0; q < D_CH / 4; q++) {
            float4 v = wq4[q];
            wqr[q * 4 + 0] = v.x; wqr[q * 4 + 1] = v.y;
            wqr[q * 4 + 2] = v.z; wqr[q * 4 + 3] = v.w;
        }
    }

    float aU[NB], aY[NB];
    #pragma unroll
    for (int b = 0; b < NB; b++) { aU[b] = 0.f; aY[b] = 0.f; }

    #pragma unroll 4
    for (int dd = 0; dd < D_CH; dd++) {
        float wq = wqr[dd];
        float wo = Wout[(size_t)(d0 + dd) * NC + c];
        #pragma unroll
        for (int b = 0; b < NB; b++) {
            aU[b] = fmaf(ks[b][dd], wq, aU[b]);
            aY[b] = fmaf(vs[b][dd], wo, aY[b]);
        }
    }
    #pragma unroll
    for (int b = 0; b < NB; b++) {
        g_upart[blockIdx.y][b * NC + c] = aU[b];
        g_ypart[blockIdx.y][b * NC + c] = aY[b];
    }
}

// ---------------------------------------------------------------------------
// k_s: fuses u-reduction. spart[ch][b,i] = sum_{c in chunk} u[b,c]*T[b,c,i]
// grid (SCH, NB) = 1024 blocks x 256; thread owns one float4 of i.
// 8 pinned LDG.128 in flight per batch (asm volatile defeats ptxas collapse).
// ---------------------------------------------------------------------------
__global__ __launch_bounds__(256) void k_s(const float* __restrict__ T) {
    __shared__ float us[C_CH];
    int b  = blockIdx.y;
    int c0 = blockIdx.x * C_CH;
    if (threadIdx.x < C_CH) {
        float u = 0.f;
        #pragma unroll
        for (int p = 0; p < KS_SPLIT; p++)
            u += g_upart[p][b * NC + c0 + threadIdx.x];
        us[threadIdx.x] = u;
    }
    __syncthreads();

    const float* Tp = T + ((size_t)b * NC + c0) * NM + 4 * threadIdx.x;
    float4 acc = {0.f, 0.f, 0.f, 0.f};
    #pragma unroll
    for (int cc = 0; cc < C_CH; cc += 8) {
        float4 t[8];
        #pragma unroll
        for (int j = 0; j < 8; j++)
            t[j] = ldg128_pin(Tp + (size_t)(cc + j) * NM);
        #pragma unroll
        for (int j = 0; j < 8; j++) {
            float u = us[cc + j];
            acc.x = fmaf(u, t[j].x, acc.x);
            acc.y = fmaf(u, t[j].y, acc.y);
            acc.z = fmaf(u, t[j].z, acc.z);
            acc.w = fmaf(u, t[j].w, acc.w);
        }
    }
    reinterpret_cast<float4*>(g_spart[blockIdx.x] + b * NM)[threadIdx.x] = acc;
}

// ---------------------------------------------------------------------------
// k_wout: fuses s-reduction + softmax + y-reduction + output write.
// grid (NM/ITILE, NB) = 256 blocks x 256 threads.
// ---------------------------------------------------------------------------
__global__ __launch_bounds__(256) void k_wout(float* __restrict__ out) {
    __shared__ __align__(16) float w_s[ITILE];
    __shared__ float y_s[NC];
    __shared__ float rs[NR];
    int b  = blockIdx.y;
    int i0 = blockIdx.x * ITILE;
    int tid = threadIdx.x;

    // phase A: rsum to smem + y reduction
    if (tid < NR) rs[tid] = g_rsum[tid];
    for (int e = tid; e < NC; e += 256) {
        float y = 0.f;
        #pragma unroll
        for (int p = 0; p < KS_SPLIT; p++)
            y += g_ypart[p][b * NC + e];
        y_s[e] = y;
    }
    __syncthreads();

    // phase B: s reduction + 64-wide softmax -> w (threads < ITILE)
    if (tid < ITILE) {
        int i = i0 + tid;
        float s = 0.f;
        #pragma unroll
        for (int p = 0; p < SCH; p++) s += g_spart[p][b * NM + i];
        s *= 0.044194173824159216f;   // 1/sqrt(512)

        float mx = -1e30f;
        #pragma unroll
        for (int r = 0; r < NR; r++) mx = fmaxf(mx, s * rs[r]);
        float sp = 0.f, spr = 0.f;
        #pragma unroll
        for (int r = 0; r < NR; r++) {
            float p = __expf(fmaf(s, rs[r], -mx));
            sp += p;
            spr = fmaf(p, rs[r], spr);
        }
        w_s[tid] = spr / sp;
    }
    __syncthreads();

    // phase C: out[b,c,i0:i0+128] = w * y[c]; 8 c's x 32 float4-lanes per pass
    int ci = tid >> 5;                 // 0..7
    int i4 = tid & 31;                 // float4 lane within i-tile
    float4 w4 = reinterpret_cast<const float4*>(w_s)[i4];
    float4* O4 = reinterpret_cast<float4*>(out);
    #pragma unroll 4
    for (int c = ci; c < NC; c += 8) {
        float yv = y_s[c];
        float4 o;
        o.x = w4.x * yv; o.y = w4.y * yv; o.z = w4.z * yv; o.w = w4.w * yv;
        O4[((size_t)(b * NC + c) * NM + i0) / 4 + i4] = o;
    }
}

// ---------------------------------------------------------------------------
extern "C" void kernel_launch(void* const* d_in, const int* in_sizes, int n_in,
                              void* d_out, int out_size) {
    const float* T    = (const float*)d_in[0];
    const float* Wq   = (const float*)d_in[1];
    const float* Wk   = (const float*)d_in[2];
    const float* Wv   = (const float*)d_in[3];
    const float* Wout = (const float*)d_in[4];
    const float* Rf   = (const float*)d_in[5];
    float* out = (float*)d_out;

    k_tsum<<<4104, 256>>>(T, Rf);
    k_p2a<<<dim3(ND / 128, CS_SPLIT), 128>>>(Wk, Wv);
    k_p2b<<<dim3(NC / 128, KS_SPLIT), 128>>>(Wq, Wout);
    k_s<<<dim3(SCH, NB), 256>>>(T);
    k_wout<<<dim3(NM / ITILE, NB), 256>>>(out);
}